// round 16
// baseline (speedup 1.0000x reference)
#include <cuda_runtime.h>
#include <cuda_bf16.h>
#include <cstdint>

// Problem constants
#define NN 16384
#define DD 1024
#define CC 1024
#define EPSV 1e-6f
#define DEN_EPS 1e-5f

// ---------------- device scratch (zero-init at load; reset by final kernel) -------
__device__ __align__(1024) __nv_bfloat16 g_fb[NN * DD];   // features bf16 (32MB)
__device__ __align__(1024) __nv_bfloat16 g_cb[CC * DD];   // centers  bf16 ( 2MB)
__device__ float g_rowterm[NN];
__device__ float g_centerterm[CC];
__device__ int   g_minmap[NN];
__device__ int   g_gcnt[128];    // per-row-block feature-conversion counters
__device__ int   g_ccnt[8];      // per-center-column conversion counters
__device__ int   g_odd_nonzero;  // labels are int32 iff set
__device__ float g_psum[64];
__device__ float g_pcnt[64];

// ---------------- helpers ---------------------------------------------------------
__device__ __forceinline__ int fmap(float f) {
    int i = __float_as_int(f);
    return i >= 0 ? i : (i ^ 0x7FFFFFFF);
}
__device__ __forceinline__ float funmap(int i) {
    return __int_as_float(i >= 0 ? i : (i ^ 0x7FFFFFFF));
}

__device__ __forceinline__ void cp16(void* dst, const void* src) {
    unsigned d = (unsigned)__cvta_generic_to_shared(dst);
    asm volatile("cp.async.cg.shared.global [%0], [%1], 16;\n" :: "r"(d), "l"(src) : "memory");
}
__device__ __forceinline__ void cp_commit() {
    asm volatile("cp.async.commit_group;\n" ::: "memory");
}
template <int N>
__device__ __forceinline__ void cp_wait() {
    asm volatile("cp.async.wait_group %0;\n" :: "n"(N) : "memory");
}

__device__ __forceinline__ void ldm_x4(uint32_t* r, uint32_t saddr) {
    asm volatile("ldmatrix.sync.aligned.m8n8.x4.shared.b16 {%0,%1,%2,%3}, [%4];\n"
                 : "=r"(r[0]), "=r"(r[1]), "=r"(r[2]), "=r"(r[3]) : "r"(saddr));
}

__device__ __forceinline__ void mma16816(float* c, const uint32_t* a,
                                         uint32_t b0, uint32_t b1) {
    asm volatile(
        "mma.sync.aligned.m16n8k16.row.col.f32.bf16.bf16.f32 "
        "{%0,%1,%2,%3}, {%4,%5,%6,%7}, {%8,%9}, {%0,%1,%2,%3};\n"
        : "+f"(c[0]), "+f"(c[1]), "+f"(c[2]), "+f"(c[3])
        : "r"(a[0]), "r"(a[1]), "r"(a[2]), "r"(a[3]), "r"(b0), "r"(b1));
}

// ---------------- warp converts ONE row --------------------------------------------
__device__ __forceinline__ void conv_row1(const float* __restrict__ src,
                                          __nv_bfloat16* dst, float* term,
                                          int row, float coef, float add) {
    const int lane = threadIdx.x & 31;
    const float4* s4 = reinterpret_cast<const float4*>(src + (size_t)row * DD);
    uint2* d2 = reinterpret_cast<uint2*>(dst + (size_t)row * DD);
    float s = 0.f, s2 = 0.f;
    #pragma unroll
    for (int i = 0; i < 8; i++) {
        float4 v = s4[i * 32 + lane];
        __nv_bfloat162 lo = __floats2bfloat162_rn(v.x, v.y);
        __nv_bfloat162 hi = __floats2bfloat162_rn(v.z, v.w);
        uint2 packed;
        packed.x = *reinterpret_cast<uint32_t*>(&lo);
        packed.y = *reinterpret_cast<uint32_t*>(&hi);
        d2[i * 32 + lane] = packed;
        s  += v.x + v.y + v.z + v.w;
        s2 += v.x * v.x + v.y * v.y + v.z * v.z + v.w * v.w;
    }
    #pragma unroll
    for (int off = 16; off; off >>= 1) {
        s  += __shfl_xor_sync(0xffffffff, s,  off);
        s2 += __shfl_xor_sync(0xffffffff, s2, off);
    }
    if (lane == 0) term[row] = s2 + coef * s + add;
}

// ---------------- warp converts 4 consecutive rows (interleaved for MLP) -----------
__device__ __forceinline__ void conv_rows4(const float* __restrict__ src,
                                           __nv_bfloat16* dst, float* term,
                                           int row0, float coef, float add) {
    const int lane = threadIdx.x & 31;
    const float4* s4 = reinterpret_cast<const float4*>(src + (size_t)row0 * DD);
    uint2* d2 = reinterpret_cast<uint2*>(dst + (size_t)row0 * DD);

    float s[4]  = {0.f, 0.f, 0.f, 0.f};
    float s2[4] = {0.f, 0.f, 0.f, 0.f};
    #pragma unroll
    for (int i = 0; i < 8; i++) {
        float4 v[4];
        #pragma unroll
        for (int rr = 0; rr < 4; rr++) v[rr] = s4[rr * 256 + i * 32 + lane];
        #pragma unroll
        for (int rr = 0; rr < 4; rr++) {
            __nv_bfloat162 lo = __floats2bfloat162_rn(v[rr].x, v[rr].y);
            __nv_bfloat162 hi = __floats2bfloat162_rn(v[rr].z, v[rr].w);
            uint2 packed;
            packed.x = *reinterpret_cast<uint32_t*>(&lo);
            packed.y = *reinterpret_cast<uint32_t*>(&hi);
            d2[rr * 256 + i * 32 + lane] = packed;
            s[rr]  += v[rr].x + v[rr].y + v[rr].z + v[rr].w;
            s2[rr] += v[rr].x * v[rr].x + v[rr].y * v[rr].y
                    + v[rr].z * v[rr].z + v[rr].w * v[rr].w;
        }
    }
    #pragma unroll
    for (int rr = 0; rr < 4; rr++) {
        #pragma unroll
        for (int off = 16; off; off >>= 1) {
            s[rr]  += __shfl_xor_sync(0xffffffff, s[rr],  off);
            s2[rr] += __shfl_xor_sync(0xffffffff, s2[rr], off);
        }
        if (lane == 0) term[row0 + rr] = s2[rr] + coef * s[rr] + add;
    }
}

// ---------------- feature conversion item (16 rows), with flags --------------------
__device__ __forceinline__ void conv_item(const float* __restrict__ f, int item,
                                          int wrp, int lane) {
    int base = item * 16 + wrp * 4;
    conv_rows4(f, g_fb, g_rowterm, base, 2.0f * EPSV, EPSV * EPSV * (float)DD);
    if (lane < 4) g_minmap[base + lane] = 0x7F800000;   // fmap(+inf)
    __threadfence();
    __syncwarp();
    if (lane == 0) atomicAdd(&g_gcnt[item >> 3], 4);
}

// ---------------- GEMM body, templated on PN (B-ldsm count; N cols = PN*32) --------
#define BM 128
#define BK 64
#define NK (DD / BK)            // 16
#define A_BYTES (BM * BK * 2)   // 16384
#define STAGE_BYTES 32768       // A 16KB + B ≤16KB (fixed stride for both tile kinds)
#define STAGES 3
#define GEMM_SMEM (STAGES * STAGE_BYTES + 16)
#define NTHREADS 128
#define NFULL 888               // full 128x128 tiles (3 clean waves at 296 slots)
#define NGRID 1160              // 888 full + 272 half (128x64)

__device__ __forceinline__ uint32_t swz(int r, int kbyte) {
    return (uint32_t)(r * 128 + (((kbyte >> 4) ^ (r & 7)) << 4) + (kbyte & 15));
}

template <int PN>   // PN=4: BN=128 ; PN=2: BN=64
__device__ __forceinline__ void gemm_min_body(char* smb, int tid, int lane,
                                              int wm, int wn, int brow, int bcol) {
    const __nv_bfloat16* Ag = g_fb + (size_t)brow * DD;
    const __nv_bfloat16* Bg = g_cb + (size_t)bcol * DD;
    const uint32_t smem0 = (uint32_t)__cvta_generic_to_shared(smb);

    uint32_t aB[4], bB[PN];
    {
        uint32_t hi16 = ((lane >> 4) & 1) << 4;
        #pragma unroll
        for (int mt = 0; mt < 4; mt++) {
            int r = wm * 64 + mt * 16 + (lane & 15);
            aB[mt] = ((uint32_t)(r * 128) | (uint32_t)((r & 7) << 4)) ^ hi16;
        }
        uint32_t hib = ((lane >> 3) & 1) << 4;
        #pragma unroll
        for (int p = 0; p < PN; p++) {
            int r = wn * (PN * 16) + p * 16 + (lane & 7) + ((lane & 16) >> 1);
            bB[p] = ((uint32_t)(r * 128) | (uint32_t)((r & 7) << 4)) ^ hib;
        }
    }

    float acc[4][2 * PN][4];
    #pragma unroll
    for (int mt = 0; mt < 4; mt++)
        #pragma unroll
        for (int nt = 0; nt < 2 * PN; nt++)
            #pragma unroll
            for (int j = 0; j < 4; j++) acc[mt][nt][j] = 0.f;

    auto stage = [&](int kt, int buf) {
        int k0 = kt * BK;
        char* As = smb + buf * STAGE_BYTES;
        char* Bs = As + A_BYTES;
        #pragma unroll
        for (int i = 0; i < 8; i++) {
            int idx = tid + i * NTHREADS;
            int r = idx >> 3, cc2 = idx & 7;
            cp16(As + swz(r, cc2 * 16), Ag + (size_t)r * DD + k0 + cc2 * 8);
        }
        #pragma unroll
        for (int i = 0; i < 2 * PN; i++) {
            int idx = tid + i * NTHREADS;
            int r = idx >> 3, cc2 = idx & 7;
            cp16(Bs + swz(r, cc2 * 16), Bg + (size_t)r * DD + k0 + cc2 * 8);
        }
        cp_commit();
    };

    stage(0, 0);
    stage(1, 1);

    for (int kt = 0; kt < NK; kt++) {
        if (kt < NK - 1) cp_wait<1>(); else cp_wait<0>();
        __syncthreads();

        const uint32_t a_base = smem0 + (uint32_t)((kt % STAGES) * STAGE_BYTES);
        const uint32_t b_base = a_base + A_BYTES;

        // ks = 0: LDSMs then MMAs immediately — cp.async burst deferred so the
        // tensor pipe refills right after the barrier instead of waiting on LSU.
        uint32_t a[4][4], b[PN][4];
        #pragma unroll
        for (int mt = 0; mt < 4; mt++) ldm_x4(a[mt], a_base + aB[mt]);
        #pragma unroll
        for (int p = 0; p < PN; p++)  ldm_x4(b[p],  b_base + bB[p]);

        #pragma unroll
        for (int mt = 0; mt < 4; mt++)
            #pragma unroll
            for (int p = 0; p < PN; p++) {
                mma16816(acc[mt][2 * p],     a[mt], b[p][0], b[p][1]);
                mma16816(acc[mt][2 * p + 1], a[mt], b[p][2], b[p][3]);
            }

        // prefetch next stage now — overlaps with ks1..ks3 math, lands 2 stages early
        if (kt + 2 < NK) stage(kt + 2, (kt + 2) % STAGES);

        #pragma unroll
        for (int ks = 1; ks < 4; ks++) {
            const uint32_t kx = (uint32_t)(ks * 32);
            #pragma unroll
            for (int mt = 0; mt < 4; mt++) ldm_x4(a[mt], a_base + (aB[mt] ^ kx));
            #pragma unroll
            for (int p = 0; p < PN; p++)  ldm_x4(b[p],  b_base + (bB[p] ^ kx));
            #pragma unroll
            for (int mt = 0; mt < 4; mt++)
                #pragma unroll
                for (int p = 0; p < PN; p++) {
                    mma16816(acc[mt][2 * p],     a[mt], b[p][0], b[p][1]);
                    mma16816(acc[mt][2 * p + 1], a[mt], b[p][2], b[p][3]);
                }
        }
    }

    // ---- fused min epilogue over this CTA's BN columns ----
    const float* ctp = g_centerterm + bcol + wn * (PN * 16) + (lane & 3) * 2;
    float ct0[2 * PN], ct1[2 * PN];
    #pragma unroll
    for (int nt = 0; nt < 2 * PN; nt++) {
        ct0[nt] = __ldg(ctp + nt * 8);
        ct1[nt] = __ldg(ctp + nt * 8 + 1);
    }
    #pragma unroll
    for (int mt = 0; mt < 4; mt++) {
        float m0 = 1e30f, m1 = 1e30f;
        #pragma unroll
        for (int nt = 0; nt < 2 * PN; nt++) {
            m0 = fminf(m0, fminf(fmaf(-2.f, acc[mt][nt][0], ct0[nt]),
                                 fmaf(-2.f, acc[mt][nt][1], ct1[nt])));
            m1 = fminf(m1, fminf(fmaf(-2.f, acc[mt][nt][2], ct0[nt]),
                                 fmaf(-2.f, acc[mt][nt][3], ct1[nt])));
        }
        #pragma unroll
        for (int off = 1; off < 4; off <<= 1) {
            m0 = fminf(m0, __shfl_xor_sync(0xffffffff, m0, off));
            m1 = fminf(m1, __shfl_xor_sync(0xffffffff, m1, off));
        }
        if ((lane & 3) == 0) {
            int r = brow + wm * 64 + mt * 16 + (lane >> 2);
            atomicMin(&g_minmap[r],     fmap(m0));
            atomicMin(&g_minmap[r + 8], fmap(m1));
        }
    }
}

// ---------------- fused convert + GEMM kernel --------------------------------------
__global__ void __launch_bounds__(NTHREADS, 2) fused_kernel(
        const float* __restrict__ f, const float* __restrict__ c,
        const unsigned int* __restrict__ lw) {
    extern __shared__ char sm_raw[];
    const int tid  = threadIdx.x;
    const int lane = tid & 31;
    const int wrp  = tid >> 5;       // 0..3
    const int bid  = blockIdx.x;
    const int wm   = wrp >> 1;       // 0..1
    const int wn   = wrp & 1;        // 0..1

    // ---- tile decode: full tiles for bid<888, half tiles (N=64) after ----
    int tile, ncol_off;
    if (bid < NFULL) { tile = bid; ncol_off = 0; }
    else { int h = bid - NFULL; tile = NFULL + (h >> 1); ncol_off = (h & 1) * 64; }
    const int row_blk = tile >> 3;
    const int brow    = row_blk * BM;
    const int bcol    = (tile & 7) * 128 + ncol_off;

    // ---- centers: bids 0..255 convert 4 rows each (1 per warp), wave-1 resident ----
    if (bid < 256) {
        int crow = bid * 4 + wrp;
        conv_row1(c, g_cb, g_centerterm, crow, -2.0f * EPSV, 0.0f);
        __threadfence();
        __syncwarp();
        if (lane == 0) atomicAdd(&g_ccnt[crow >> 7], 1);
    } else if (bid < 320) {
        // labels dtype detect: 64 CTAs scan all 8192 odd words
        int i = (bid - 256) * 256 + tid * 2 + 1;
        if (lw[i] != 0u) atomicOr(&g_odd_nonzero, 1);
        if (lw[i + 128] != 0u) atomicOr(&g_odd_nonzero, 1);
    }

    // ---- feature conversion duty (exact partition of items 0..1023) ----
    // bids 0..887: item = bid.  bids 296..431: ALSO item 888+(bid-296).
    if (bid < NFULL) conv_item(f, bid, wrp, lane);
    if (bid >= 296 && bid < 432) conv_item(f, 888 + (bid - 296), wrp, lane);

    // ---- wait for this tile's center column + feature row group ----
    if (tid == 0) {
        volatile int* cd = &g_ccnt[tile & 7];
        while (*cd < 128) __nanosleep(64);
        volatile int* gc = &g_gcnt[row_blk];
        while (*gc < BM) __nanosleep(64);
        __threadfence();
    }
    __syncthreads();

    if (bid < NFULL) gemm_min_body<4>(sm_raw, tid, lane, wm, wn, brow, bcol);
    else             gemm_min_body<2>(sm_raw, tid, lane, wm, wn, brow, bcol);
}

// ---------------- masked reduction: 64-block partials + tiny final -----------------
__global__ void __launch_bounds__(256) reduce_kernel(
        const unsigned int* __restrict__ lw) {
    const int b   = blockIdx.x;
    const int row = b * 256 + threadIdx.x;
    const bool lab64 = (g_odd_nonzero == 0);
    const void* labels = (const void*)lw;

    float m    = funmap(g_minmap[row]);
    float sq   = g_rowterm[row] + m;
    float dist = sqrtf(fmaxf(sq, 0.f));
    long long lab = lab64 ? ((const long long*)labels)[row]
                          : (long long)((const int*)labels)[row];
    float s = (lab == 0) ? dist : 0.f;
    float c = (lab == 0) ? 1.f : 0.f;

    #pragma unroll
    for (int off = 16; off; off >>= 1) {
        s += __shfl_xor_sync(0xffffffff, s, off);
        c += __shfl_xor_sync(0xffffffff, c, off);
    }
    __shared__ float sh[2][8];
    const int w = threadIdx.x >> 5, l = threadIdx.x & 31;
    if (l == 0) { sh[0][w] = s; sh[1][w] = c; }
    __syncthreads();
    if (threadIdx.x == 0) {
        float ts = 0.f, tc = 0.f;
        #pragma unroll
        for (int i = 0; i < 8; i++) { ts += sh[0][i]; tc += sh[1][i]; }
        g_psum[b] = ts;
        g_pcnt[b] = tc;
    }
}

__global__ void final_kernel(float* __restrict__ out) {
    int t = threadIdx.x;   // 32 threads
    float s = g_psum[t] + g_psum[t + 32];
    float c = g_pcnt[t] + g_pcnt[t + 32];
    #pragma unroll
    for (int off = 16; off; off >>= 1) {
        s += __shfl_xor_sync(0xffffffff, s, off);
        c += __shfl_xor_sync(0xffffffff, c, off);
    }
    if (t == 0) out[0] = s / (c + DEN_EPS);

    // reset replay state (graph replays reuse module globals)
    #pragma unroll
    for (int i = 0; i < 4; i++) g_gcnt[t * 4 + i] = 0;
    if (t < 8) g_ccnt[t] = 0;
    if (t == 8) g_odd_nonzero = 0;
}

// ---------------- launch --------------------------------------------------------------
extern "C" void kernel_launch(void* const* d_in, const int* in_sizes, int n_in,
                              void* d_out, int out_size) {
    const float* features = (const float*)d_in[0];
    const void*  labels   = d_in[1];
    const float* centers  = (const float*)d_in[2];
    float* out = (float*)d_out;

    cudaFuncSetAttribute(fused_kernel,
                         cudaFuncAttributeMaxDynamicSharedMemorySize, GEMM_SMEM);

    fused_kernel<<<NGRID, NTHREADS, GEMM_SMEM>>>(
        features, centers, (const unsigned int*)labels);
    reduce_kernel<<<64, 256>>>((const unsigned int*)labels);
    final_kernel<<<1, 32>>>(out);
}

// round 17
// speedup vs baseline: 1.0612x; 1.0612x over previous
#include <cuda_runtime.h>
#include <cuda_bf16.h>
#include <cstdint>

// Problem constants
#define NN 16384
#define DD 1024
#define CC 1024
#define EPSV 1e-6f
#define DEN_EPS 1e-5f

// ---------------- device scratch (zero-init at load; reset by final kernel) -------
__device__ __align__(1024) __nv_bfloat16 g_fb[NN * DD];   // features bf16 (32MB)
__device__ __align__(1024) __nv_bfloat16 g_cb[CC * DD];   // centers  bf16 ( 2MB)
__device__ float g_rowterm[NN];
__device__ float g_centerterm[CC];
__device__ int   g_minmap[NN];
__device__ int   g_gcnt[128];    // per-row-block feature-conversion counters
__device__ int   g_ccnt[8];      // per-center-column conversion counters
__device__ float g_psum[64];
__device__ float g_pcnt[64];

// ---------------- helpers ---------------------------------------------------------
__device__ __forceinline__ int fmap(float f) {
    int i = __float_as_int(f);
    return i >= 0 ? i : (i ^ 0x7FFFFFFF);
}
__device__ __forceinline__ float funmap(int i) {
    return __int_as_float(i >= 0 ? i : (i ^ 0x7FFFFFFF));
}

__device__ __forceinline__ void cp16(void* dst, const void* src) {
    unsigned d = (unsigned)__cvta_generic_to_shared(dst);
    asm volatile("cp.async.cg.shared.global [%0], [%1], 16;\n" :: "r"(d), "l"(src) : "memory");
}
__device__ __forceinline__ void cp_commit() {
    asm volatile("cp.async.commit_group;\n" ::: "memory");
}
template <int N>
__device__ __forceinline__ void cp_wait() {
    asm volatile("cp.async.wait_group %0;\n" :: "n"(N) : "memory");
}

__device__ __forceinline__ void ldm_x4(uint32_t* r, uint32_t saddr) {
    asm volatile("ldmatrix.sync.aligned.m8n8.x4.shared.b16 {%0,%1,%2,%3}, [%4];\n"
                 : "=r"(r[0]), "=r"(r[1]), "=r"(r[2]), "=r"(r[3]) : "r"(saddr));
}

__device__ __forceinline__ void mma16816(float* c, const uint32_t* a,
                                         uint32_t b0, uint32_t b1) {
    asm volatile(
        "mma.sync.aligned.m16n8k16.row.col.f32.bf16.bf16.f32 "
        "{%0,%1,%2,%3}, {%4,%5,%6,%7}, {%8,%9}, {%0,%1,%2,%3};\n"
        : "+f"(c[0]), "+f"(c[1]), "+f"(c[2]), "+f"(c[3])
        : "r"(a[0]), "r"(a[1]), "r"(a[2]), "r"(a[3]), "r"(b0), "r"(b1));
}

// ---------------- warp converts ONE row --------------------------------------------
__device__ __forceinline__ void conv_row1(const float* __restrict__ src,
                                          __nv_bfloat16* dst, float* term,
                                          int row, float coef, float add) {
    const int lane = threadIdx.x & 31;
    const float4* s4 = reinterpret_cast<const float4*>(src + (size_t)row * DD);
    uint2* d2 = reinterpret_cast<uint2*>(dst + (size_t)row * DD);
    float s = 0.f, s2 = 0.f;
    #pragma unroll
    for (int i = 0; i < 8; i++) {
        float4 v = s4[i * 32 + lane];
        __nv_bfloat162 lo = __floats2bfloat162_rn(v.x, v.y);
        __nv_bfloat162 hi = __floats2bfloat162_rn(v.z, v.w);
        uint2 packed;
        packed.x = *reinterpret_cast<uint32_t*>(&lo);
        packed.y = *reinterpret_cast<uint32_t*>(&hi);
        d2[i * 32 + lane] = packed;
        s  += v.x + v.y + v.z + v.w;
        s2 += v.x * v.x + v.y * v.y + v.z * v.z + v.w * v.w;
    }
    #pragma unroll
    for (int off = 16; off; off >>= 1) {
        s  += __shfl_xor_sync(0xffffffff, s,  off);
        s2 += __shfl_xor_sync(0xffffffff, s2, off);
    }
    if (lane == 0) term[row] = s2 + coef * s + add;
}

// ---------------- warp converts 4 consecutive rows (interleaved for MLP) -----------
__device__ __forceinline__ void conv_rows4(const float* __restrict__ src,
                                           __nv_bfloat16* dst, float* term,
                                           int row0, float coef, float add) {
    const int lane = threadIdx.x & 31;
    const float4* s4 = reinterpret_cast<const float4*>(src + (size_t)row0 * DD);
    uint2* d2 = reinterpret_cast<uint2*>(dst + (size_t)row0 * DD);

    float s[4]  = {0.f, 0.f, 0.f, 0.f};
    float s2[4] = {0.f, 0.f, 0.f, 0.f};
    #pragma unroll
    for (int i = 0; i < 8; i++) {
        float4 v[4];
        #pragma unroll
        for (int rr = 0; rr < 4; rr++) v[rr] = s4[rr * 256 + i * 32 + lane];
        #pragma unroll
        for (int rr = 0; rr < 4; rr++) {
            __nv_bfloat162 lo = __floats2bfloat162_rn(v[rr].x, v[rr].y);
            __nv_bfloat162 hi = __floats2bfloat162_rn(v[rr].z, v[rr].w);
            uint2 packed;
            packed.x = *reinterpret_cast<uint32_t*>(&lo);
            packed.y = *reinterpret_cast<uint32_t*>(&hi);
            d2[rr * 256 + i * 32 + lane] = packed;
            s[rr]  += v[rr].x + v[rr].y + v[rr].z + v[rr].w;
            s2[rr] += v[rr].x * v[rr].x + v[rr].y * v[rr].y
                    + v[rr].z * v[rr].z + v[rr].w * v[rr].w;
        }
    }
    #pragma unroll
    for (int rr = 0; rr < 4; rr++) {
        #pragma unroll
        for (int off = 16; off; off >>= 1) {
            s[rr]  += __shfl_xor_sync(0xffffffff, s[rr],  off);
            s2[rr] += __shfl_xor_sync(0xffffffff, s2[rr], off);
        }
        if (lane == 0) term[row0 + rr] = s2[rr] + coef * s[rr] + add;
    }
}

// ---------------- feature conversion item (16 rows), with flags --------------------
__device__ __forceinline__ void conv_item(const float* __restrict__ f, int item,
                                          int wrp, int lane) {
    int base = item * 16 + wrp * 4;
    conv_rows4(f, g_fb, g_rowterm, base, 2.0f * EPSV, EPSV * EPSV * (float)DD);
    if (lane < 4) g_minmap[base + lane] = 0x7F800000;   // fmap(+inf)
    __threadfence();
    __syncwarp();
    if (lane == 0) atomicAdd(&g_gcnt[item >> 3], 4);
}

// ---------------- GEMM body, templated on PN (B-ldsm count; N cols = PN*32) --------
#define BM 128
#define BK 64
#define NK (DD / BK)            // 16
#define A_BYTES (BM * BK * 2)   // 16384
#define STAGE_BYTES 32768       // A 16KB + B ≤16KB (fixed stride for both tile kinds)
#define STAGES 3
#define GEMM_SMEM (STAGES * STAGE_BYTES + 16)
#define NTHREADS 128
#define NFULL 888               // full 128x128 tiles (3 clean waves at 296 slots)
#define NGRID 1160              // 888 full + 272 half (128x64)

__device__ __forceinline__ uint32_t swz(int r, int kbyte) {
    return (uint32_t)(r * 128 + (((kbyte >> 4) ^ (r & 7)) << 4) + (kbyte & 15));
}

template <int PN>   // PN=4: BN=128 ; PN=2: BN=64
__device__ __forceinline__ void gemm_min_body(char* smb, int tid, int lane,
                                              int wm, int wn, int brow, int bcol) {
    const __nv_bfloat16* Ag = g_fb + (size_t)brow * DD;
    const __nv_bfloat16* Bg = g_cb + (size_t)bcol * DD;
    const uint32_t smem0 = (uint32_t)__cvta_generic_to_shared(smb);

    uint32_t aB[4], bB[PN];
    {
        uint32_t hi16 = ((lane >> 4) & 1) << 4;
        #pragma unroll
        for (int mt = 0; mt < 4; mt++) {
            int r = wm * 64 + mt * 16 + (lane & 15);
            aB[mt] = ((uint32_t)(r * 128) | (uint32_t)((r & 7) << 4)) ^ hi16;
        }
        uint32_t hib = ((lane >> 3) & 1) << 4;
        #pragma unroll
        for (int p = 0; p < PN; p++) {
            int r = wn * (PN * 16) + p * 16 + (lane & 7) + ((lane & 16) >> 1);
            bB[p] = ((uint32_t)(r * 128) | (uint32_t)((r & 7) << 4)) ^ hib;
        }
    }

    float acc[4][2 * PN][4];
    #pragma unroll
    for (int mt = 0; mt < 4; mt++)
        #pragma unroll
        for (int nt = 0; nt < 2 * PN; nt++)
            #pragma unroll
            for (int j = 0; j < 4; j++) acc[mt][nt][j] = 0.f;

    auto stage = [&](int kt, int buf) {
        int k0 = kt * BK;
        char* As = smb + buf * STAGE_BYTES;
        char* Bs = As + A_BYTES;
        #pragma unroll
        for (int i = 0; i < 8; i++) {
            int idx = tid + i * NTHREADS;
            int r = idx >> 3, cc2 = idx & 7;
            cp16(As + swz(r, cc2 * 16), Ag + (size_t)r * DD + k0 + cc2 * 8);
        }
        #pragma unroll
        for (int i = 0; i < 2 * PN; i++) {
            int idx = tid + i * NTHREADS;
            int r = idx >> 3, cc2 = idx & 7;
            cp16(Bs + swz(r, cc2 * 16), Bg + (size_t)r * DD + k0 + cc2 * 8);
        }
        cp_commit();
    };

    stage(0, 0);
    stage(1, 1);

    for (int kt = 0; kt < NK; kt++) {
        if (kt < NK - 1) cp_wait<1>(); else cp_wait<0>();
        __syncthreads();

        const uint32_t a_base = smem0 + (uint32_t)((kt % STAGES) * STAGE_BYTES);
        const uint32_t b_base = a_base + A_BYTES;

        // ks = 0: LDSMs first, THEN prefetch burst, THEN MMAs (R13 ordering —
        // measured optimum of the three orderings tested).
        uint32_t a[4][4], b[PN][4];
        #pragma unroll
        for (int mt = 0; mt < 4; mt++) ldm_x4(a[mt], a_base + aB[mt]);
        #pragma unroll
        for (int p = 0; p < PN; p++)  ldm_x4(b[p],  b_base + bB[p]);

        if (kt + 2 < NK) stage(kt + 2, (kt + 2) % STAGES);

        #pragma unroll
        for (int mt = 0; mt < 4; mt++)
            #pragma unroll
            for (int p = 0; p < PN; p++) {
                mma16816(acc[mt][2 * p],     a[mt], b[p][0], b[p][1]);
                mma16816(acc[mt][2 * p + 1], a[mt], b[p][2], b[p][3]);
            }

        #pragma unroll
        for (int ks = 1; ks < 4; ks++) {
            const uint32_t kx = (uint32_t)(ks * 32);
            #pragma unroll
            for (int mt = 0; mt < 4; mt++) ldm_x4(a[mt], a_base + (aB[mt] ^ kx));
            #pragma unroll
            for (int p = 0; p < PN; p++)  ldm_x4(b[p],  b_base + (bB[p] ^ kx));
            #pragma unroll
            for (int mt = 0; mt < 4; mt++)
                #pragma unroll
                for (int p = 0; p < PN; p++) {
                    mma16816(acc[mt][2 * p],     a[mt], b[p][0], b[p][1]);
                    mma16816(acc[mt][2 * p + 1], a[mt], b[p][2], b[p][3]);
                }
        }
    }

    // ---- fused min epilogue over this CTA's BN columns ----
    const float* ctp = g_centerterm + bcol + wn * (PN * 16) + (lane & 3) * 2;
    float ct0[2 * PN], ct1[2 * PN];
    #pragma unroll
    for (int nt = 0; nt < 2 * PN; nt++) {
        ct0[nt] = __ldg(ctp + nt * 8);
        ct1[nt] = __ldg(ctp + nt * 8 + 1);
    }
    #pragma unroll
    for (int mt = 0; mt < 4; mt++) {
        float m0 = 1e30f, m1 = 1e30f;
        #pragma unroll
        for (int nt = 0; nt < 2 * PN; nt++) {
            m0 = fminf(m0, fminf(fmaf(-2.f, acc[mt][nt][0], ct0[nt]),
                                 fmaf(-2.f, acc[mt][nt][1], ct1[nt])));
            m1 = fminf(m1, fminf(fmaf(-2.f, acc[mt][nt][2], ct0[nt]),
                                 fmaf(-2.f, acc[mt][nt][3], ct1[nt])));
        }
        #pragma unroll
        for (int off = 1; off < 4; off <<= 1) {
            m0 = fminf(m0, __shfl_xor_sync(0xffffffff, m0, off));
            m1 = fminf(m1, __shfl_xor_sync(0xffffffff, m1, off));
        }
        if ((lane & 3) == 0) {
            int r = brow + wm * 64 + mt * 16 + (lane >> 2);
            atomicMin(&g_minmap[r],     fmap(m0));
            atomicMin(&g_minmap[r + 8], fmap(m1));
        }
    }
}

// ---------------- fused convert + GEMM kernel --------------------------------------
__global__ void __launch_bounds__(NTHREADS, 2) fused_kernel(
        const float* __restrict__ f, const float* __restrict__ c) {
    extern __shared__ char sm_raw[];
    const int tid  = threadIdx.x;
    const int lane = tid & 31;
    const int wrp  = tid >> 5;       // 0..3
    const int bid  = blockIdx.x;
    const int wm   = wrp >> 1;       // 0..1
    const int wn   = wrp & 1;        // 0..1

    // ---- tile decode: full tiles for bid<888, half tiles (N=64) after ----
    int tile, ncol_off;
    if (bid < NFULL) { tile = bid; ncol_off = 0; }
    else { int h = bid - NFULL; tile = NFULL + (h >> 1); ncol_off = (h & 1) * 64; }
    const int row_blk = tile >> 3;
    const int brow    = row_blk * BM;
    const int bcol    = (tile & 7) * 128 + ncol_off;

    // ---- centers: bids 0..255 convert 4 rows each (1 per warp), wave-1 resident ----
    if (bid < 256) {
        int crow = bid * 4 + wrp;
        conv_row1(c, g_cb, g_centerterm, crow, -2.0f * EPSV, 0.0f);
        __threadfence();
        __syncwarp();
        if (lane == 0) atomicAdd(&g_ccnt[crow >> 7], 1);
    }

    // ---- feature conversion duty (exact partition of items 0..1023) ----
    // bids 0..887: item = bid.  Tail items 888..1023 spread over bids 296+3j
    // (waves 2-3) so no single CTA group bears all the double duty.
    if (bid < NFULL) conv_item(f, bid, wrp, lane);
    if (bid >= 296 && bid < 296 + 3 * 136 && ((bid - 296) % 3) == 0)
        conv_item(f, 888 + (bid - 296) / 3, wrp, lane);

    // ---- wait for this tile's center column + feature row group ----
    if (tid == 0) {
        volatile int* cd = &g_ccnt[tile & 7];
        while (*cd < 128) __nanosleep(64);
        volatile int* gc = &g_gcnt[row_blk];
        while (*gc < BM) __nanosleep(64);
        __threadfence();
    }
    __syncthreads();

    if (bid < NFULL) gemm_min_body<4>(sm_raw, tid, lane, wm, wn, brow, bcol);
    else             gemm_min_body<2>(sm_raw, tid, lane, wm, wn, brow, bcol);
}

// ---------------- masked reduction: 64-block partials + tiny final -----------------
__global__ void __launch_bounds__(256) reduce_kernel(
        const unsigned int* __restrict__ lw) {
    const int b   = blockIdx.x;
    const int tid = threadIdx.x;
    const int row = b * 256 + tid;

    // local labels-dtype detect: odd words of this block's 256 rows
    __shared__ int s_odd;
    if (tid == 0) s_odd = 0;
    __syncthreads();
    if (lw[row * 2 + 1] != 0u) atomicOr(&s_odd, 1);   // safe for int32 too (in-bounds)
    __syncthreads();
    const bool lab64 = (s_odd == 0);
    const void* labels = (const void*)lw;

    float m    = funmap(g_minmap[row]);
    float sq   = g_rowterm[row] + m;
    float dist = sqrtf(fmaxf(sq, 0.f));
    long long lab = lab64 ? ((const long long*)labels)[row]
                          : (long long)((const int*)labels)[row];
    float s = (lab == 0) ? dist : 0.f;
    float c = (lab == 0) ? 1.f : 0.f;

    #pragma unroll
    for (int off = 16; off; off >>= 1) {
        s += __shfl_xor_sync(0xffffffff, s, off);
        c += __shfl_xor_sync(0xffffffff, c, off);
    }
    __shared__ float sh[2][8];
    const int w = tid >> 5, l = tid & 31;
    if (l == 0) { sh[0][w] = s; sh[1][w] = c; }
    __syncthreads();
    if (tid == 0) {
        float ts = 0.f, tc = 0.f;
        #pragma unroll
        for (int i = 0; i < 8; i++) { ts += sh[0][i]; tc += sh[1][i]; }
        g_psum[b] = ts;
        g_pcnt[b] = tc;
    }
}

__global__ void final_kernel(float* __restrict__ out) {
    int t = threadIdx.x;   // 32 threads
    float s = g_psum[t] + g_psum[t + 32];
    float c = g_pcnt[t] + g_pcnt[t + 32];
    #pragma unroll
    for (int off = 16; off; off >>= 1) {
        s += __shfl_xor_sync(0xffffffff, s, off);
        c += __shfl_xor_sync(0xffffffff, c, off);
    }
    if (t == 0) out[0] = s / (c + DEN_EPS);

    // reset replay state (graph replays reuse module globals)
    #pragma unroll
    for (int i = 0; i < 4; i++) g_gcnt[t * 4 + i] = 0;
    if (t < 8) g_ccnt[t] = 0;
}

// ---------------- launch --------------------------------------------------------------
extern "C" void kernel_launch(void* const* d_in, const int* in_sizes, int n_in,
                              void* d_out, int out_size) {
    const float* features = (const float*)d_in[0];
    const void*  labels   = d_in[1];
    const float* centers  = (const float*)d_in[2];
    float* out = (float*)d_out;

    cudaFuncSetAttribute(fused_kernel,
                         cudaFuncAttributeMaxDynamicSharedMemorySize, GEMM_SMEM);

    fused_kernel<<<NGRID, NTHREADS, GEMM_SMEM>>>(features, centers);
    reduce_kernel<<<64, 256>>>((const unsigned int*)labels);
    final_kernel<<<1, 32>>>(out);
}